// round 1
// baseline (speedup 1.0000x reference)
#include <cuda_runtime.h>

// Problem: B=2048 rows, N=8192 cols.
// Per row: r = |y_true - y_pred|; Newton (20 iters) for eps s.t. mean(sinh(r/eps))=1;
// beta = 1/(eps+1e-6); q = sinh(beta*r); q_norm = q/(max q + 1e-20);
// Lambda' = 0.99*Lambda + 0.1*(0.9*q_norm + 0.1);
// loss = mean((Lambda' * r)^2) over all B*N.
// Output layout: d_out[0] = loss, d_out[1..B*N] = Lambda' (row-major).

#define BDIM 1024
#define VPT 8

static constexpr int B = 2048;
static constexpr int N = 8192;
// ln(2*N) = ln(16384) = 14*ln(2)
static constexpr float LOG_2N = 9.70406052783923f;

__device__ float g_row_loss[B];

__device__ __forceinline__ float warp_sum(float v) {
#pragma unroll
    for (int o = 16; o; o >>= 1) v += __shfl_xor_sync(0xffffffffu, v, o);
    return v;
}
__device__ __forceinline__ float warp_max(float v) {
#pragma unroll
    for (int o = 16; o; o >>= 1) v = fmaxf(v, __shfl_xor_sync(0xffffffffu, v, o));
    return v;
}

__global__ __launch_bounds__(BDIM, 2)
void custom_loss_row_kernel(const float* __restrict__ y_pred,
                            const float* __restrict__ y_true,
                            const float* __restrict__ Lam,
                            float* __restrict__ out_lambda) {
    const int b = blockIdx.x;
    const size_t base = (size_t)b * N;
    const int t = threadIdx.x;
    const int lane = t & 31;
    const int wid = t >> 5;

    __shared__ float s1s[32];
    __shared__ float s2s[32];
    __shared__ float bcast;

    // Load residuals into registers (coalesced, stride-BDIM layout)
    float r[VPT];
#pragma unroll
    for (int i = 0; i < VPT; i++) {
        const int idx = t + i * BDIM;
        r[i] = fabsf(y_true[base + idx] - y_pred[base + idx]);
    }

    // ---- row max(r) ----
    float m = r[0];
#pragma unroll
    for (int i = 1; i < VPT; i++) m = fmaxf(m, r[i]);
    m = warp_max(m);
    if (lane == 0) s1s[wid] = m;
    __syncthreads();
    if (t < 32) {
        float v = warp_max(s1s[t]);
        if (t == 0) bcast = v;
    }
    __syncthreads();
    const float rmax = bcast;

    float eps = fmaxf(rmax, 1e-8f) / (LOG_2N + 1e-8f);

    // ---- 20 Newton iterations for eps : mean(sinh(r/eps)) = 1 ----
    const float invN = 1.0f / (float)N;
    for (int itn = 0; itn < 20; itn++) {
        const float eps_safe = fmaxf(eps, 1e-8f);
        const float inv = __fdividef(1.0f, eps_safe);
        float a = 0.0f;  // sum (e^u - e^-u)      -> 2*sum sinh(u)
        float c = 0.0f;  // sum (e^u + e^-u) * u  -> 2*sum u*cosh(u)
#pragma unroll
        for (int i = 0; i < VPT; i++) {
            const float u = r[i] * inv;
            const float e  = __expf(u);
            const float em = __expf(-u);
            a += (e - em);
            c += (e + em) * u;
        }
        a = warp_sum(a);
        c = warp_sum(c);
        if (lane == 0) { s1s[wid] = a; s2s[wid] = c; }
        __syncthreads();
        if (t < 32) {
            float a2 = warp_sum(s1s[t]);
            float c2 = warp_sum(s2s[t]);
            if (t == 0) {
                const float val  = 0.5f * a2 * invN - 1.0f;
                const float grad = -0.5f * c2 * invN * inv;
                bcast = eps - __fdividef(val, (grad - 1e-8f));
            }
        }
        __syncthreads();
        eps = bcast;
        // (bcast is only rewritten after the next iteration's first __syncthreads,
        //  and s1s/s2s are only rewritten after this point too -> safe.)
    }

    eps = fmaxf(eps, 1e-8f);
    const float beta = __fdividef(1.0f, eps + 1e-6f);

    // ---- q = sinh(beta * r), row max ----
    float q[VPT];
    float qm = 0.0f;  // q >= 0 since r >= 0
#pragma unroll
    for (int i = 0; i < VPT; i++) {
        const float u = r[i] * beta;
        const float e  = __expf(u);
        const float em = __expf(-u);
        q[i] = 0.5f * (e - em);
        qm = fmaxf(qm, q[i]);
    }
    qm = warp_max(qm);
    if (lane == 0) s1s[wid] = qm;
    __syncthreads();
    if (t < 32) {
        float v = warp_max(s1s[t]);
        if (t == 0) bcast = v;
    }
    __syncthreads();
    const float inv_qm = __fdividef(1.0f, bcast + 1e-20f);

    // ---- Lambda update + per-row loss partial ----
    float lsum = 0.0f;
#pragma unroll
    for (int i = 0; i < VPT; i++) {
        const int idx = t + i * BDIM;
        const float qn = q[i] * inv_qm;
        const float lam_it = 0.9f * qn + 0.1f;                  // PHI*qn + (1-PHI)
        const float lam = 0.99f * Lam[base + idx] + 0.1f * lam_it;  // GAMMA*L + ETA*lam_it
        out_lambda[base + idx] = lam;
        const float z = lam * r[i];
        lsum += z * z;
    }
    lsum = warp_sum(lsum);
    if (lane == 0) s1s[wid] = lsum;
    __syncthreads();
    if (t < 32) {
        float v = warp_sum(s1s[t]);
        if (t == 0) g_row_loss[b] = v;
    }
}

__global__ void loss_reduce_kernel(float* __restrict__ out_loss) {
    const int t = threadIdx.x;  // 1024 threads
    float s = g_row_loss[t] + g_row_loss[t + 1024];
    s = warp_sum(s);
    __shared__ float sm[32];
    if ((t & 31) == 0) sm[t >> 5] = s;
    __syncthreads();
    if (t < 32) {
        float v = warp_sum(sm[t]);
        if (t == 0) out_loss[0] = v * (1.0f / 16777216.0f);  // / (B*N)
    }
}

extern "C" void kernel_launch(void* const* d_in, const int* in_sizes, int n_in,
                              void* d_out, int out_size) {
    const float* y_pred = (const float*)d_in[0];
    const float* y_true = (const float*)d_in[1];
    const float* Lam    = (const float*)d_in[2];
    // d_in[3] = it (unused by the cosh branch)

    float* out = (float*)d_out;           // out[0] = loss
    float* out_lambda = out + 1;          // out[1..] = updated Lambda

    custom_loss_row_kernel<<<B, BDIM>>>(y_pred, y_true, Lam, out_lambda);
    loss_reduce_kernel<<<1, BDIM>>>(out);
}

// round 2
// speedup vs baseline: 2.9905x; 2.9905x over previous
#include <cuda_runtime.h>

// B=2048 rows, N=8192 cols.
// Per row: r = |y_true - y_pred|; solve mean(sinh(r/eps))=1 (Newton in beta=1/eps
// on h(beta)=log(mean sinh(beta*r)), same unique root as the reference's 20
// eps-space Newton iterations, converged to f32 roundoff, early-exit);
// beta_f = 1/(eps+1e-6); q = sinh(beta_f*r); q_norm = q/(max q + 1e-20);
// Lambda' = 0.99*Lambda + 0.1*(0.9*q_norm + 0.1);
// loss = mean((Lambda' * r)^2).
// Output: d_out[0] = loss, d_out[1..B*N] = Lambda' (row-major).

#define BDIM 1024
#define VPT 8

static constexpr int B = 2048;
static constexpr int N = 8192;
static constexpr float LOG_2N = 9.70406052783923f;  // ln(2*N) = ln(16384)

__device__ float g_row_loss[B];

__device__ __forceinline__ float warp_sum(float v) {
#pragma unroll
    for (int o = 16; o; o >>= 1) v += __shfl_xor_sync(0xffffffffu, v, o);
    return v;
}
__device__ __forceinline__ float warp_max(float v) {
#pragma unroll
    for (int o = 16; o; o >>= 1) v = fmaxf(v, __shfl_xor_sync(0xffffffffu, v, o));
    return v;
}

__global__ __launch_bounds__(BDIM)
void custom_loss_row_kernel(const float* __restrict__ y_pred,
                            const float* __restrict__ y_true,
                            const float* __restrict__ Lam,
                            float* __restrict__ out_lambda) {
    const int b = blockIdx.x;
    const size_t base = (size_t)b * N;
    const int t = threadIdx.x;
    const int lane = t & 31;
    const int wid = t >> 5;

    __shared__ float s1s[32];
    __shared__ float s2s[32];
    __shared__ float bcast;
    __shared__ int   sdone;

    // ---- residuals: float4 loads, 8 elems/thread ----
    const float4* yp4 = (const float4*)(y_pred + base);
    const float4* yt4 = (const float4*)(y_true + base);
    const float4 p0 = yp4[t],        g0 = yt4[t];
    const float4 p1 = yp4[t + BDIM], g1 = yt4[t + BDIM];
    float r[VPT];
    r[0] = fabsf(g0.x - p0.x); r[1] = fabsf(g0.y - p0.y);
    r[2] = fabsf(g0.z - p0.z); r[3] = fabsf(g0.w - p0.w);
    r[4] = fabsf(g1.x - p1.x); r[5] = fabsf(g1.y - p1.y);
    r[6] = fabsf(g1.z - p1.z); r[7] = fabsf(g1.w - p1.w);

    // ---- row max(r) ----
    float m = r[0];
#pragma unroll
    for (int i = 1; i < VPT; i++) m = fmaxf(m, r[i]);
    m = warp_max(m);
    if (lane == 0) s1s[wid] = m;
    __syncthreads();
    if (t < 32) {
        float v = warp_max(s1s[t]);
        if (t == 0) bcast = v;
    }
    __syncthreads();
    const float rmax = bcast;

    // beta0 = 1/eps0 with eps0 = max(rmax,1e-8)/(ln(2N)+1e-8)  (reference init)
    float beta = (LOG_2N + 1e-8f) / fmaxf(rmax, 1e-8f);

    // ---- Newton in beta on h(beta) = log(mean sinh(beta*r)) = 0 ----
    // h concave increasing, beta0 above root -> step 1 brackets from below,
    // then monotone quadratic convergence. Early-exit on relative step.
    for (int itn = 0; itn < 20; itn++) {
        float S = 0.0f;  // sum (e^u - e^-u)       = 2*sum sinh(u)
        float T = 0.0f;  // sum (e^u + e^-u) * r   = 2*sum r*cosh(u)
#pragma unroll
        for (int i = 0; i < VPT; i++) {
            const float x  = beta * r[i];
            const float E  = __expf(x);
            const float Em = __expf(-x);
            S += (E - Em);
            T = fmaf(E + Em, r[i], T);
        }
        S = warp_sum(S);
        T = warp_sum(T);
        if (lane == 0) { s1s[wid] = S; s2s[wid] = T; }
        __syncthreads();
        if (t < 32) {
            float S2 = warp_sum(s1s[t]);
            float T2 = warp_sum(s2s[t]);
            if (t == 0) {
                // mean sinh = S2/(2N);  h = log(S2) - log(2N);  h' = T2/S2
                const float h  = __logf(S2) - LOG_2N;
                float db = h * __fdividef(S2, T2);
                float nb = beta - db;
                nb = fmaxf(nb, 0.05f * beta);  // safety clamp (never hit in practice)
                bcast = nb;
                sdone = (fabsf(db) < 1e-6f * beta) ? 1 : 0;
            }
        }
        __syncthreads();
        beta = bcast;
        if (sdone) break;  // uniform across block
    }

    // ---- final beta exactly as reference: eps floor, then +1e-6 ----
    float eps = fmaxf(__fdividef(1.0f, beta), 1e-8f);
    const float betaF = __fdividef(1.0f, eps + 1e-6f);

    // ---- q = sinh(betaF * r), row max ----
    float q[VPT];
    float qm = 0.0f;  // q >= 0 since r >= 0
#pragma unroll
    for (int i = 0; i < VPT; i++) {
        const float x  = betaF * r[i];
        const float E  = __expf(x);
        const float Em = __expf(-x);
        q[i] = 0.5f * (E - Em);
        qm = fmaxf(qm, q[i]);
    }
    qm = warp_max(qm);
    if (lane == 0) s1s[wid] = qm;
    __syncthreads();
    if (t < 32) {
        float v = warp_max(s1s[t]);
        if (t == 0) bcast = v;
    }
    __syncthreads();
    const float inv_qm = __fdividef(1.0f, bcast + 1e-20f);

    // ---- Lambda update (float4 loads, scalar stores: out base is +1 float,
    //      so 16B-misaligned) + per-row loss partial ----
    const float4* L4 = (const float4*)(Lam + base);
    const float4 l0 = L4[t], l1 = L4[t + BDIM];
    const float lamv[VPT] = {l0.x, l0.y, l0.z, l0.w, l1.x, l1.y, l1.z, l1.w};

    float lsum = 0.0f;
#pragma unroll
    for (int i = 0; i < VPT; i++) {
        const int idx = (i < 4) ? (4 * t + i) : (4 * (t + BDIM) + (i - 4));
        const float qn = q[i] * inv_qm;
        const float lam_it = fmaf(0.9f, qn, 0.1f);            // PHI*qn + (1-PHI)
        const float lam = fmaf(0.99f, lamv[i], 0.1f * lam_it); // GAMMA*L + ETA*lam_it
        out_lambda[base + idx] = lam;
        const float z = lam * r[i];
        lsum = fmaf(z, z, lsum);
    }
    lsum = warp_sum(lsum);
    if (lane == 0) s1s[wid] = lsum;
    __syncthreads();
    if (t < 32) {
        float v = warp_sum(s1s[t]);
        if (t == 0) g_row_loss[b] = v;
    }
}

__global__ void loss_reduce_kernel(float* __restrict__ out_loss) {
    const int t = threadIdx.x;  // 1024 threads
    float s = g_row_loss[t] + g_row_loss[t + 1024];
    s = warp_sum(s);
    __shared__ float sm[32];
    if ((t & 31) == 0) sm[t >> 5] = s;
    __syncthreads();
    if (t < 32) {
        float v = warp_sum(sm[t]);
        if (t == 0) out_loss[0] = v * (1.0f / 16777216.0f);  // / (B*N)
    }
}

extern "C" void kernel_launch(void* const* d_in, const int* in_sizes, int n_in,
                              void* d_out, int out_size) {
    const float* y_pred = (const float*)d_in[0];
    const float* y_true = (const float*)d_in[1];
    const float* Lam    = (const float*)d_in[2];
    // d_in[3] = it (unused by the cosh branch)

    float* out = (float*)d_out;       // out[0] = loss
    float* out_lambda = out + 1;      // out[1..] = updated Lambda

    custom_loss_row_kernel<<<B, BDIM>>>(y_pred, y_true, Lam, out_lambda);
    loss_reduce_kernel<<<1, BDIM>>>(out);
}